// round 5
// baseline (speedup 1.0000x reference)
#include <cuda_runtime.h>
#include <cuda_bf16.h>

#define ETA     0.5f
#define KAPPA   0.1f

__device__ __forceinline__ float warp_sum(float v) {
    #pragma unroll
    for (int o = 16; o > 0; o >>= 1)
        v += __shfl_xor_sync(0xFFFFFFFFu, v, o);
    return v;
}

__device__ __forceinline__ float dot4(float4 v) {
    return v.x*v.x + v.y*v.y + v.z*v.z + v.w*v.w;
}

// One CTA per batch row.
__global__ __launch_bounds__(256, 8)
void soliton_kernel(const float* __restrict__ residue,
                    const float* __restrict__ cons,
                    const float* __restrict__ pert,
                    float* __restrict__ out,
                    int B, int S, int D)
{
    const int b    = blockIdx.x;
    const int tid  = threadIdx.x;
    const int nthr = blockDim.x;

    // ---- perturbation row: S*D contiguous floats, float4 + deep MLP ----
    const float4* __restrict__ p4 =
        reinterpret_cast<const float4*>(pert + (size_t)b * S * D);
    const int n4 = (S * D) >> 2;   // 25600 for S=100, D=1024

    float a0 = 0.f, a1 = 0.f, a2 = 0.f, a3 = 0.f;
    int i = tid;
    // 8 independent streaming loads in flight per thread, 4 acc chains
    for (; i + 7 * nthr < n4; i += 8 * nthr) {
        float4 v0 = __ldcs(p4 + i);
        float4 v1 = __ldcs(p4 + i + nthr);
        float4 v2 = __ldcs(p4 + i + 2 * nthr);
        float4 v3 = __ldcs(p4 + i + 3 * nthr);
        float4 v4 = __ldcs(p4 + i + 4 * nthr);
        float4 v5 = __ldcs(p4 + i + 5 * nthr);
        float4 v6 = __ldcs(p4 + i + 6 * nthr);
        float4 v7 = __ldcs(p4 + i + 7 * nthr);
        a0 += dot4(v0);
        a1 += dot4(v1);
        a2 += dot4(v2);
        a3 += dot4(v3);
        a0 += dot4(v4);
        a1 += dot4(v5);
        a2 += dot4(v6);
        a3 += dot4(v7);
    }
    // remainder (4 iterations/thread for n4=25600, nthr=256)
    for (; i < n4; i += nthr) {
        a0 += dot4(__ldcs(p4 + i));
    }
    float pacc = (a0 + a1) + (a2 + a3);

    // ---- residue / constraint rows: D floats each (cacheable) ----
    const float4* __restrict__ r4 =
        reinterpret_cast<const float4*>(residue + (size_t)b * D);
    const float4* __restrict__ c4 =
        reinterpret_cast<const float4*>(cons + (size_t)b * D);
    const int d4 = D >> 2;

    float eacc = 0.0f, cacc = 0.0f;
    for (int j = tid; j < d4; j += nthr) {
        float4 rv = r4[j];
        float4 cv = c4[j];
        eacc += dot4(rv);
        cacc += dot4(cv);
    }

    // ---- block reduction ----
    __shared__ float sp[8], se[8], sc[8];
    float wp = warp_sum(pacc);
    float we = warp_sum(eacc);
    float wc = warp_sum(cacc);
    const int wid = tid >> 5;
    const int lid = tid & 31;
    if (lid == 0) { sp[wid] = wp; se[wid] = we; sc[wid] = wc; }
    __syncthreads();

    if (tid == 0) {
        float psum = 0.0f, esum = 0.0f, csum = 0.0f;
        const int nw = nthr >> 5;
        #pragma unroll
        for (int w = 0; w < 8; w++) {
            if (w < nw) { psum += sp[w]; esum += se[w]; csum += sc[w]; }
        }

        float dispersion = psum / (float)S;
        float energy     = esum;
        float cscale     = sqrtf(csum);
        float edensity   = energy / (cscale + 1e-8f);
        float loc        = (energy > 0.0f) ? (ETA / (edensity + 1e-8f)) : cscale;
        float ratio      = dispersion / (loc + 1e-8f);

        out[b]         = (ratio < KAPPA) ? 1.0f : 0.0f;  // is_soliton
        out[B + b]     = dispersion;
        out[2 * B + b] = loc;
        out[3 * B + b] = ratio;
    }
}

extern "C" void kernel_launch(void* const* d_in, const int* in_sizes, int n_in,
                              void* d_out, int out_size)
{
    const float* residue = (const float*)d_in[0];
    const float* cons    = (const float*)d_in[1];
    const float* pert    = (const float*)d_in[2];
    float*       out     = (float*)d_out;

    const int D = 1024;
    const int B = in_sizes[0] / D;                 // 1024
    const int S = in_sizes[2] / in_sizes[0];       // 100

    soliton_kernel<<<B, 256>>>(residue, cons, pert, out, B, S, D);
}

// round 8
// speedup vs baseline: 1.0584x; 1.0584x over previous
#include <cuda_runtime.h>
#include <cuda_bf16.h>

#define ETA     0.5f
#define KAPPA   0.1f

__device__ __forceinline__ float warp_sum(float v) {
    #pragma unroll
    for (int o = 16; o > 0; o >>= 1)
        v += __shfl_xor_sync(0xFFFFFFFFu, v, o);
    return v;
}

__device__ __forceinline__ float dot4(float4 v) {
    return v.x*v.x + v.y*v.y + v.z*v.z + v.w*v.w;
}

// Specialized: D=1024, S=100, 256 threads, one CTA per batch row.
// Per thread: exactly 100 float4 pert loads (25 x 4-deep MLP), 1 float4
// residue load, 1 float4 cons load. MLP_p1 kept at 4 to avoid cross-CTA
// L1tex queue contention at occ~7-8 (measured regression at MLP 8).
template<int D, int S, int NTHR>
__global__ __launch_bounds__(NTHR, 8)
void soliton_kernel_t(const float* __restrict__ residue,
                      const float* __restrict__ cons,
                      const float* __restrict__ pert,
                      float* __restrict__ out,
                      int B)
{
    const int b   = blockIdx.x;
    const int tid = threadIdx.x;

    constexpr int N4    = (S * D) / 4;      // 25600
    constexpr int ITERS = N4 / NTHR;        // 100
    constexpr int OUTER = ITERS / 4;        // 25
    static_assert(ITERS * NTHR == N4, "exact tiling");
    static_assert(OUTER * 4 == ITERS, "exact tiling");

    const float4* __restrict__ p4 =
        reinterpret_cast<const float4*>(pert) + (size_t)b * N4;

    float a0 = 0.f, a1 = 0.f, a2 = 0.f, a3 = 0.f;
    int i = tid;
    #pragma unroll 1
    for (int k = 0; k < OUTER; k++, i += 4 * NTHR) {
        float4 v0 = p4[i];
        float4 v1 = p4[i + NTHR];
        float4 v2 = p4[i + 2 * NTHR];
        float4 v3 = p4[i + 3 * NTHR];
        a0 += dot4(v0);
        a1 += dot4(v1);
        a2 += dot4(v2);
        a3 += dot4(v3);
    }
    float pacc = (a0 + a1) + (a2 + a3);

    // ---- residue / constraint rows: exactly one float4 per thread ----
    constexpr int D4 = D / 4;               // 256 == NTHR
    static_assert(D4 == NTHR, "one load per thread");
    const float4* __restrict__ r4 =
        reinterpret_cast<const float4*>(residue) + (size_t)b * D4;
    const float4* __restrict__ c4 =
        reinterpret_cast<const float4*>(cons) + (size_t)b * D4;

    float eacc = dot4(r4[tid]);
    float cacc = dot4(c4[tid]);

    // ---- block reduction ----
    __shared__ float sp[NTHR / 32], se[NTHR / 32], sc[NTHR / 32];
    float wp = warp_sum(pacc);
    float we = warp_sum(eacc);
    float wc = warp_sum(cacc);
    const int wid = tid >> 5;
    const int lid = tid & 31;
    if (lid == 0) { sp[wid] = wp; se[wid] = we; sc[wid] = wc; }
    __syncthreads();

    if (tid == 0) {
        float psum = 0.f, esum = 0.f, csum = 0.f;
        #pragma unroll
        for (int w = 0; w < NTHR / 32; w++) {
            psum += sp[w]; esum += se[w]; csum += sc[w];
        }

        float dispersion = psum / (float)S;
        float energy     = esum;
        float cscale     = sqrtf(csum);
        float edensity   = energy / (cscale + 1e-8f);
        float loc        = (energy > 0.0f) ? (ETA / (edensity + 1e-8f)) : cscale;
        float ratio      = dispersion / (loc + 1e-8f);

        out[b]         = (ratio < KAPPA) ? 1.0f : 0.0f;  // is_soliton
        out[B + b]     = dispersion;
        out[2 * B + b] = loc;
        out[3 * B + b] = ratio;
    }
}

// Generic fallback (any B, S, D with D % 4 == 0)
__global__ __launch_bounds__(256, 8)
void soliton_kernel_g(const float* __restrict__ residue,
                      const float* __restrict__ cons,
                      const float* __restrict__ pert,
                      float* __restrict__ out,
                      int B, int S, int D)
{
    const int b    = blockIdx.x;
    const int tid  = threadIdx.x;
    const int nthr = blockDim.x;

    const float4* __restrict__ p4 =
        reinterpret_cast<const float4*>(pert + (size_t)b * S * D);
    const int n4 = (S * D) >> 2;

    float a0 = 0.f, a1 = 0.f, a2 = 0.f, a3 = 0.f;
    int i = tid;
    for (; i + 3 * nthr < n4; i += 4 * nthr) {
        float4 v0 = p4[i];
        float4 v1 = p4[i + nthr];
        float4 v2 = p4[i + 2 * nthr];
        float4 v3 = p4[i + 3 * nthr];
        a0 += dot4(v0); a1 += dot4(v1); a2 += dot4(v2); a3 += dot4(v3);
    }
    for (; i < n4; i += nthr) a0 += dot4(p4[i]);
    float pacc = (a0 + a1) + (a2 + a3);

    const float4* __restrict__ r4 =
        reinterpret_cast<const float4*>(residue + (size_t)b * D);
    const float4* __restrict__ c4 =
        reinterpret_cast<const float4*>(cons + (size_t)b * D);
    const int d4 = D >> 2;

    float eacc = 0.f, cacc = 0.f;
    for (int j = tid; j < d4; j += nthr) {
        eacc += dot4(r4[j]);
        cacc += dot4(c4[j]);
    }

    __shared__ float sp[8], se[8], sc[8];
    float wp = warp_sum(pacc);
    float we = warp_sum(eacc);
    float wc = warp_sum(cacc);
    const int wid = tid >> 5;
    const int lid = tid & 31;
    if (lid == 0) { sp[wid] = wp; se[wid] = we; sc[wid] = wc; }
    __syncthreads();

    if (tid == 0) {
        float psum = 0.f, esum = 0.f, csum = 0.f;
        const int nw = nthr >> 5;
        for (int w = 0; w < nw; w++) { psum += sp[w]; esum += se[w]; csum += sc[w]; }

        float dispersion = psum / (float)S;
        float energy     = esum;
        float cscale     = sqrtf(csum);
        float edensity   = energy / (cscale + 1e-8f);
        float loc        = (energy > 0.0f) ? (ETA / (edensity + 1e-8f)) : cscale;
        float ratio      = dispersion / (loc + 1e-8f);

        out[b]         = (ratio < KAPPA) ? 1.0f : 0.0f;
        out[B + b]     = dispersion;
        out[2 * B + b] = loc;
        out[3 * B + b] = ratio;
    }
}

extern "C" void kernel_launch(void* const* d_in, const int* in_sizes, int n_in,
                              void* d_out, int out_size)
{
    const float* residue = (const float*)d_in[0];
    const float* cons    = (const float*)d_in[1];
    const float* pert    = (const float*)d_in[2];
    float*       out     = (float*)d_out;

    const int D = 1024;
    const int B = in_sizes[0] / D;                 // 1024
    const int S = in_sizes[2] / in_sizes[0];       // 100

    if (D == 1024 && S == 100 && B > 0) {
        soliton_kernel_t<1024, 100, 256><<<B, 256>>>(residue, cons, pert, out, B);
    } else {
        soliton_kernel_g<<<B, 256>>>(residue, cons, pert, out, B, S, D);
    }
}